// round 6
// baseline (speedup 1.0000x reference)
#include <cuda_runtime.h>
#include <math.h>
#include <stdint.h>

#define B_ 4
#define S_ 2048
#define HID_ 1024
#define NH_ 16
#define HD_ 64
#define LOG2E 1.4426950408889634f

// Scratch: rounded+k-permuted inputs, Q/K/V in [B*NH, S, HD] layout.
// g_h/g_w/g_k use the k-permutation pos(u)=2*(u&3)+(u>>2) within 8-groups.
__device__ float g_h[B_ * S_ * HID_];
__device__ float g_w[3][HID_ * HID_];
__device__ float g_q[B_ * NH_ * S_ * HD_];
__device__ float g_k[B_ * NH_ * S_ * HD_];
__device__ float g_v[B_ * NH_ * S_ * HD_];

// ===========================================================================
// PTX helpers (sm_103 base ISA only)
// ===========================================================================
__device__ __forceinline__ uint32_t smem_u32(const void* p) {
    uint32_t a;
    asm("{ .reg .u64 t; cvta.to.shared.u64 t, %1; cvt.u32.u64 %0, t; }"
        : "=r"(a) : "l"(p));
    return a;
}

__device__ __forceinline__ uint32_t f2tf32(float x) {
    uint32_t r;
    asm("cvt.rna.tf32.f32 %0, %1;" : "=r"(r) : "f"(x));
    return r;
}

__device__ __forceinline__ float ex2(float x) {
    float r;
    asm("ex2.approx.f32 %0, %1;" : "=f"(r) : "f"(x));
    return r;
}

__device__ __forceinline__ void mma_tf32(float* d, const uint32_t* a, const uint32_t* b) {
    asm volatile(
        "mma.sync.aligned.m16n8k8.row.col.f32.tf32.tf32.f32 "
        "{%0,%1,%2,%3}, {%4,%5,%6,%7}, {%8,%9}, {%0,%1,%2,%3};"
        : "+f"(d[0]), "+f"(d[1]), "+f"(d[2]), "+f"(d[3])
        : "r"(a[0]), "r"(a[1]), "r"(a[2]), "r"(a[3]), "r"(b[0]), "r"(b[1]));
}

__device__ __forceinline__ void mma_tf32b(float* d, const uint32_t* a,
                                          uint32_t b0, uint32_t b1) {
    asm volatile(
        "mma.sync.aligned.m16n8k8.row.col.f32.tf32.tf32.f32 "
        "{%0,%1,%2,%3}, {%4,%5,%6,%7}, {%8,%9}, {%0,%1,%2,%3};"
        : "+f"(d[0]), "+f"(d[1]), "+f"(d[2]), "+f"(d[3])
        : "r"(a[0]), "r"(a[1]), "r"(a[2]), "r"(a[3]), "r"(b0), "r"(b1));
}

__device__ __forceinline__ void cp16(uint32_t dst, const void* src) {
    asm volatile("cp.async.cg.shared.global [%0], [%1], 16;"
                 :: "r"(dst), "l"(src) : "memory");
}
#define CP_COMMIT() asm volatile("cp.async.commit_group;" ::: "memory")
#define CP_WAIT1()  asm volatile("cp.async.wait_group 1;" ::: "memory")
#define CP_WAIT0()  asm volatile("cp.async.wait_group 0;" ::: "memory")

__device__ __forceinline__ void mulf2(float2& d, float a) {
    float2 s = make_float2(a, a);
    asm("mul.rn.f32x2 %0, %0, %1;"
        : "+l"(*reinterpret_cast<unsigned long long*>(&d))
        : "l"(*reinterpret_cast<const unsigned long long*>(&s)));
}

// ===========================================================================
// Prologue: rna-round H and W into scratch WITH k-permutation.
// float4 covers k = 4j..4j+3 (all same 8-group half): perm positions are
// base + {0,2,4,6} + (j&1).
// ===========================================================================
#define HN4 (B_ * S_ * HID_ / 4)
#define WN4 (HID_ * HID_ / 4)
#define RND_BLOCKS ((HN4 + 3 * WN4) / 256)

__global__ __launch_bounds__(256) void round_inputs(
    const float* __restrict__ H, const float* __restrict__ Wq,
    const float* __restrict__ Wk, const float* __restrict__ Wv)
{
    const int i = blockIdx.x * 256 + threadIdx.x;
    const float* src;
    float* dst;
    int j = i;
    if (j < HN4) { src = H; dst = g_h; }
    else if ((j -= HN4) < WN4) { src = Wq; dst = g_w[0]; }
    else if ((j -= WN4) < WN4) { src = Wk; dst = g_w[1]; }
    else { j -= WN4; src = Wv; dst = g_w[2]; }
    float4 v = ((const float4*)src)[j];
    const int base = (j * 4) & ~7;
    const int off  = j & 1;
    dst[base + off + 0] = __uint_as_float(f2tf32(v.x));
    dst[base + off + 2] = __uint_as_float(f2tf32(v.y));
    dst[base + off + 4] = __uint_as_float(f2tf32(v.z));
    dst[base + off + 6] = __uint_as_float(f2tf32(v.w));
}

// ===========================================================================
// QKV projection via mma.sync tf32 + cp.async 3-stage pipeline.
// Fragment loads are LDS.64 thanks to the k-permutation in g_h/g_w.
// K-projection output is written d-permuted (for attn's LDS.64 K frags).
// ===========================================================================
#define QLDA 36
#define QSTG_W (128 * QLDA)
#define QB_OFF (3 * QSTG_W)
#define QKV_SMEM (6 * QSTG_W * 4)

extern __shared__ uint32_t qkv_sm[];

__global__ __launch_bounds__(256) void qkv_mma(
    const float* __restrict__ bq, const float* __restrict__ bk,
    const float* __restrict__ bv)
{
    const int proj = blockIdx.z;
    const float* Wsel = g_w[proj];
    const float* bias = (proj == 0) ? bq : (proj == 1) ? bk : bv;
    float* out        = (proj == 0) ? g_q : (proj == 1) ? g_k : g_v;

    const int m0 = blockIdx.y * 128;
    const int n0 = blockIdx.x * 128;

    const int t    = threadIdx.x;
    const int lane = t & 31;
    const int wid  = t >> 5;
    const int wm   = wid & 3;
    const int wn   = wid >> 2;
    const int g    = lane >> 2;
    const int tig  = lane & 3;

    const uint32_t sbase = smem_u32(qkv_sm);

    float acc[2][8][4];
    #pragma unroll
    for (int i = 0; i < 2; i++)
        #pragma unroll
        for (int j = 0; j < 8; j++)
            #pragma unroll
            for (int c = 0; c < 4; c++) acc[i][j][c] = 0.0f;

    auto cp_stage = [&](int st, int slot) {
        const int k0 = st * 32;
        const float* hA = g_h + (size_t)m0 * HID_ + k0;
        const float* wB = Wsel + (size_t)n0 * HID_ + k0;
        #pragma unroll
        for (int j = 0; j < 4; j++) {
            const int c = t + j * 256;
            const int r = c >> 3, cc = (c & 7) * 4;
            cp16(sbase + (uint32_t)(slot * QSTG_W + r * QLDA + cc) * 4,
                 hA + (size_t)r * HID_ + cc);
            cp16(sbase + (uint32_t)(QB_OFF + slot * QSTG_W + r * QLDA + cc) * 4,
                 wB + (size_t)r * HID_ + cc);
        }
    };

    cp_stage(0, 0); CP_COMMIT();
    cp_stage(1, 1); CP_COMMIT();

    for (int s = 0; s < 32; s++) {
        CP_WAIT1();
        __syncthreads();
        if (s + 2 < 32) cp_stage(s + 2, (s + 2) % 3);
        CP_COMMIT();

        const uint32_t* A  = qkv_sm + (s % 3) * QSTG_W;
        const uint32_t* Bs = qkv_sm + QB_OFF + (s % 3) * QSTG_W;

        #pragma unroll
        for (int kk = 0; kk < 4; kk++) {
            const int kb = kk * 8;
            uint32_t af[2][4], bf[8][2];
            #pragma unroll
            for (int tm = 0; tm < 2; tm++) {
                const int mr = wm * 32 + tm * 16;
                uint2 lo = *(const uint2*)&A[(mr + g) * QLDA + kb + 2 * tig];
                uint2 hi = *(const uint2*)&A[(mr + g + 8) * QLDA + kb + 2 * tig];
                af[tm][0] = lo.x; af[tm][1] = hi.x;
                af[tm][2] = lo.y; af[tm][3] = hi.y;
            }
            #pragma unroll
            for (int tn = 0; tn < 8; tn++) {
                const int nr = wn * 64 + tn * 8;
                uint2 bb = *(const uint2*)&Bs[(nr + g) * QLDA + kb + 2 * tig];
                bf[tn][0] = bb.x; bf[tn][1] = bb.y;
            }
            #pragma unroll
            for (int tm = 0; tm < 2; tm++)
                #pragma unroll
                for (int tn = 0; tn < 8; tn++)
                    mma_tf32(acc[tm][tn], af[tm], bf[tn]);
        }
    }

    // Epilogue (rna-rounded). K goes out d-permuted; Q/V normal.
    #pragma unroll
    for (int tm = 0; tm < 2; tm++) {
        const int m = m0 + wm * 32 + tm * 16 + g;
        const int bb = m >> 11;
        const int ss = m & 2047;
        #pragma unroll
        for (int tn = 0; tn < 8; tn++) {
            const int n = n0 + wn * 64 + tn * 8 + tig * 2;
            const int h = n >> 6;
            const int d = n & 63;
            const float2 bv2 = *(const float2*)(bias + n);
            float* base = out + ((size_t)(bb * NH_ + h) * S_) * HD_;
            const float v00 = __uint_as_float(f2tf32(acc[tm][tn][0] + bv2.x));
            const float v01 = __uint_as_float(f2tf32(acc[tm][tn][1] + bv2.y));
            const float v10 = __uint_as_float(f2tf32(acc[tm][tn][2] + bv2.x));
            const float v11 = __uint_as_float(f2tf32(acc[tm][tn][3] + bv2.y));
            if (proj != 1) {
                float2 o0 = make_float2(v00, v01);
                float2 o1 = make_float2(v10, v11);
                *(float2*)(base + (size_t)ss * HD_ + d) = o0;
                *(float2*)(base + (size_t)(ss + 8) * HD_ + d) = o1;
            } else {
                // d&7 = 2*tig; perm positions: pos0 = pos(2tig), pos0+2
                const int dbase = d - 2 * tig;
                const int pos0 = ((tig & 1) << 2) | (tig >> 1);
                float* r0 = base + (size_t)ss * HD_ + dbase;
                float* r1 = base + (size_t)(ss + 8) * HD_ + dbase;
                r0[pos0] = v00; r0[pos0 + 2] = v01;
                r1[pos0] = v10; r1[pos0 + 2] = v11;
            }
        }
    }
}

// ===========================================================================
// Flash attention via mma.sync tf32 + cp.async double-buffered K/V.
// Single __syncthreads per KV tile; K fragments via LDS.64 (g_k d-permuted).
// ===========================================================================
#define LDK 68
#define LDV 68
#define LDP 68
#define KVBUF_W 4352
#define VS_OFF 8704
#define PS_OFF 17408
#define MSK_OFF 26112
#define AT_SMEM ((MSK_OFF + 2048) * 4)

extern __shared__ uint32_t at_sm[];

__global__ void __launch_bounds__(256, 2) attn_mma(
    const float* __restrict__ mask, float* __restrict__ out)
{
    const int bh = blockIdx.y;
    const int bb = bh >> 4;
    const int h  = bh & 15;
    const int q0 = blockIdx.x * 128;

    const float* Q = g_q + (size_t)bh * S_ * HD_;
    const float* K = g_k + (size_t)bh * S_ * HD_;
    const float* V = g_v + (size_t)bh * S_ * HD_;
    const float* mrow = mask + (size_t)bb * S_;

    const int t    = threadIdx.x;
    const int lane = t & 31;
    const int w    = t >> 5;
    const int g    = lane >> 2;
    const int tig  = lane & 3;

    const uint32_t sbase = smem_u32(at_sm);
    float* msk = (float*)(at_sm + MSK_OFF);

    #pragma unroll
    for (int i = t; i < 512; i += 256) {
        float4 m4 = ((const float4*)mrow)[i];
        m4.x *= LOG2E; m4.y *= LOG2E; m4.z *= LOG2E; m4.w *= LOG2E;
        ((float4*)msk)[i] = m4;
    }

    const float SC = 0.125f * LOG2E;
    uint32_t qf[8][4];
    {
        const float* q0p = Q + (size_t)(q0 + w * 16 + g) * HD_;
        const float* q1p = q0p + 8 * HD_;
        #pragma unroll
        for (int kb = 0; kb < 8; kb++) {
            qf[kb][0] = f2tf32(SC * q0p[kb * 8 + tig]);
            qf[kb][1] = f2tf32(SC * q1p[kb * 8 + tig]);
            qf[kb][2] = f2tf32(SC * q0p[kb * 8 + tig + 4]);
            qf[kb][3] = f2tf32(SC * q1p[kb * 8 + tig + 4]);
        }
    }

    auto cp_tile = [&](int tile, int buf) {
        const int kv0 = tile * 64;
        #pragma unroll
        for (int j = 0; j < 4; j++) {
            const int c = t + j * 256;
            const int r = c >> 4, cc = (c & 15) * 4;
            cp16(sbase + (uint32_t)(buf * KVBUF_W + r * LDK + cc) * 4,
                 K + (size_t)(kv0 + r) * HD_ + cc);
            cp16(sbase + (uint32_t)(VS_OFF + buf * KVBUF_W + r * LDV + cc) * 4,
                 V + (size_t)(kv0 + r) * HD_ + cc);
        }
    };

    cp_tile(0, 0); CP_COMMIT();

    float2 oa[8][2];
    #pragma unroll
    for (int nt = 0; nt < 8; nt++) {
        oa[nt][0] = make_float2(0.f, 0.f);
        oa[nt][1] = make_float2(0.f, 0.f);
    }
    float m0 = -INFINITY, m1 = -INFINITY, l0 = 0.0f, l1 = 0.0f;

    for (int it = 0; it < 32; it++) {
        const int buf = it & 1;
        CP_WAIT0();        // tile it arrived (issued last iter, flew over compute)
        __syncthreads();   // all warps done with compute(it-1): buf^1 reusable
        if (it + 1 < 32) cp_tile(it + 1, buf ^ 1);
        CP_COMMIT();

        const uint32_t* Ks = at_sm + buf * KVBUF_W;
        const uint32_t* Vs = at_sm + VS_OFF + buf * KVBUF_W;
        uint32_t* Ps = at_sm + PS_OFF + w * (16 * LDP);
        const float* mk_s = msk + it * 64;

        // S = Q K^T (log2 domain); K fragments are LDS.64 (d-permuted)
        float sacc[8][4];
        #pragma unroll
        for (int nt = 0; nt < 8; nt++)
            #pragma unroll
            for (int c = 0; c < 4; c++) sacc[nt][c] = 0.0f;

        #pragma unroll
        for (int kb = 0; kb < 8; kb++) {
            const uint32_t* kp = Ks + g * LDK + kb * 8 + 2 * tig;
            #pragma unroll
            for (int nt = 0; nt < 8; nt++) {
                uint2 b = *(const uint2*)&kp[nt * 8 * LDK];
                mma_tf32b(sacc[nt], qf[kb], b.x, b.y);
            }
        }

        float mx0 = m0, mx1 = m1;
        #pragma unroll
        for (int nt = 0; nt < 8; nt++) {
            const float2 mk = *(const float2*)&mk_s[nt * 8 + 2 * tig];
            sacc[nt][0] += mk.x; sacc[nt][1] += mk.y;
            sacc[nt][2] += mk.x; sacc[nt][3] += mk.y;
            mx0 = fmaxf(mx0, fmaxf(sacc[nt][0], sacc[nt][1]));
            mx1 = fmaxf(mx1, fmaxf(sacc[nt][2], sacc[nt][3]));
        }
        mx0 = fmaxf(mx0, __shfl_xor_sync(0xffffffffu, mx0, 1));
        mx0 = fmaxf(mx0, __shfl_xor_sync(0xffffffffu, mx0, 2));
        mx1 = fmaxf(mx1, __shfl_xor_sync(0xffffffffu, mx1, 1));
        mx1 = fmaxf(mx1, __shfl_xor_sync(0xffffffffu, mx1, 2));

        const float alpha0 = ex2(m0 - mx0);
        const float alpha1 = ex2(m1 - mx1);
        m0 = mx0; m1 = mx1;

        float s0 = 0.0f, s1 = 0.0f;
        #pragma unroll
        for (int nt = 0; nt < 8; nt++) {
            const uint32_t u0 = f2tf32(ex2(sacc[nt][0] - mx0));
            const uint32_t u1 = f2tf32(ex2(sacc[nt][1] - mx0));
            const uint32_t u2 = f2tf32(ex2(sacc[nt][2] - mx1));
            const uint32_t u3 = f2tf32(ex2(sacc[nt][3] - mx1));
            s0 += __uint_as_float(u0) + __uint_as_float(u1);
            s1 += __uint_as_float(u2) + __uint_as_float(u3);
            *(uint2*)&Ps[g * LDP + nt * 8 + 2 * tig] = make_uint2(u0, u1);
            *(uint2*)&Ps[(g + 8) * LDP + nt * 8 + 2 * tig] = make_uint2(u2, u3);
        }
        s0 += __shfl_xor_sync(0xffffffffu, s0, 1);
        s0 += __shfl_xor_sync(0xffffffffu, s0, 2);
        s1 += __shfl_xor_sync(0xffffffffu, s1, 1);
        s1 += __shfl_xor_sync(0xffffffffu, s1, 2);
        l0 = l0 * alpha0 + s0;
        l1 = l1 * alpha1 + s1;

        #pragma unroll
        for (int nt = 0; nt < 8; nt++) {
            mulf2(oa[nt][0], alpha0);
            mulf2(oa[nt][1], alpha1);
        }
        __syncwarp();

        // O += P V
        #pragma unroll
        for (int kb = 0; kb < 8; kb++) {
            uint32_t a[4];
            a[0] = Ps[g * LDP + kb * 8 + tig];
            a[1] = Ps[(g + 8) * LDP + kb * 8 + tig];
            a[2] = Ps[g * LDP + kb * 8 + tig + 4];
            a[3] = Ps[(g + 8) * LDP + kb * 8 + tig + 4];
            const uint32_t* vp = Vs + (kb * 8 + tig) * LDV + g;
            #pragma unroll
            for (int nt = 0; nt < 8; nt++)
                mma_tf32b((float*)&oa[nt][0], a,
                          vp[nt * 8], vp[4 * LDV + nt * 8]);
        }
    }

    const float inv0 = 1.0f / l0;
    const float inv1 = 1.0f / l1;
    const int r0 = q0 + w * 16 + g;
    float* o0 = out + ((size_t)(bb * S_ + r0)) * HID_ + h * 64;
    float* o1 = out + ((size_t)(bb * S_ + r0 + 8)) * HID_ + h * 64;
    #pragma unroll
    for (int nt = 0; nt < 8; nt++) {
        const int c = nt * 8 + 2 * tig;
        float2 v0, v1;
        v0.x = oa[nt][0].x * inv0; v0.y = oa[nt][0].y * inv0;
        v1.x = oa[nt][1].x * inv1; v1.y = oa[nt][1].y * inv1;
        *(float2*)(o0 + c) = v0;
        *(float2*)(o1 + c) = v1;
    }
}

// ===========================================================================
extern "C" void kernel_launch(void* const* d_in, const int* in_sizes, int n_in,
                              void* d_out, int out_size)
{
    const float* H    = (const float*)d_in[0];
    const float* mask = (const float*)d_in[1];
    const float* Wq   = (const float*)d_in[2];
    const float* bq   = (const float*)d_in[3];
    const float* Wk   = (const float*)d_in[4];
    const float* bk   = (const float*)d_in[5];
    const float* Wv   = (const float*)d_in[6];
    const float* bv   = (const float*)d_in[7];
    float* out = (float*)d_out;

    cudaFuncSetAttribute(qkv_mma,
                         cudaFuncAttributeMaxDynamicSharedMemorySize, QKV_SMEM);
    cudaFuncSetAttribute(attn_mma,
                         cudaFuncAttributeMaxDynamicSharedMemorySize, AT_SMEM);

    round_inputs<<<RND_BLOCKS, 256>>>(H, Wq, Wk, Wv);

    dim3 gq(HID_ / 128, (B_ * S_) / 128, 3);
    qkv_mma<<<gq, 256, QKV_SMEM>>>(bq, bk, bv);

    dim3 ga(S_ / 128, B_ * NH_);
    attn_mma<<<ga, 256, AT_SMEM>>>(mask, out);
}

// round 7
// speedup vs baseline: 1.2075x; 1.2075x over previous
#include <cuda_runtime.h>
#include <math.h>
#include <stdint.h>

#define B_ 4
#define S_ 2048
#define HID_ 1024
#define NH_ 16
#define HD_ 64
#define LOG2E 1.4426950408889634f

// Scratch: rounded inputs + Q/K/V in [B*NH, S, HD] layout.
// g_k's d-dimension is permuted within 8-groups: pos(u)=2*(u&3)+(u>>2).
__device__ float g_h[B_ * S_ * HID_];
__device__ float g_w[3][HID_ * HID_];
__device__ float g_q[B_ * NH_ * S_ * HD_];
__device__ float g_k[B_ * NH_ * S_ * HD_];
__device__ float g_v[B_ * NH_ * S_ * HD_];

// ===========================================================================
// PTX helpers (sm_103 base ISA only)
// ===========================================================================
__device__ __forceinline__ uint32_t smem_u32(const void* p) {
    uint32_t a;
    asm("{ .reg .u64 t; cvta.to.shared.u64 t, %1; cvt.u32.u64 %0, t; }"
        : "=r"(a) : "l"(p));
    return a;
}

__device__ __forceinline__ uint32_t f2tf32(float x) {
    uint32_t r;
    asm("cvt.rna.tf32.f32 %0, %1;" : "=r"(r) : "f"(x));
    return r;
}

__device__ __forceinline__ float ex2(float x) {
    float r;
    asm("ex2.approx.f32 %0, %1;" : "=f"(r) : "f"(x));
    return r;
}

__device__ __forceinline__ void mma_tf32(float* d, const uint32_t* a, const uint32_t* b) {
    asm volatile(
        "mma.sync.aligned.m16n8k8.row.col.f32.tf32.tf32.f32 "
        "{%0,%1,%2,%3}, {%4,%5,%6,%7}, {%8,%9}, {%0,%1,%2,%3};"
        : "+f"(d[0]), "+f"(d[1]), "+f"(d[2]), "+f"(d[3])
        : "r"(a[0]), "r"(a[1]), "r"(a[2]), "r"(a[3]), "r"(b[0]), "r"(b[1]));
}

__device__ __forceinline__ void mma_tf32b(float* d, const uint32_t* a,
                                          uint32_t b0, uint32_t b1) {
    asm volatile(
        "mma.sync.aligned.m16n8k8.row.col.f32.tf32.tf32.f32 "
        "{%0,%1,%2,%3}, {%4,%5,%6,%7}, {%8,%9}, {%0,%1,%2,%3};"
        : "+f"(d[0]), "+f"(d[1]), "+f"(d[2]), "+f"(d[3])
        : "r"(a[0]), "r"(a[1]), "r"(a[2]), "r"(a[3]), "r"(b0), "r"(b1));
}

__device__ __forceinline__ void cp16(uint32_t dst, const void* src) {
    asm volatile("cp.async.cg.shared.global [%0], [%1], 16;"
                 :: "r"(dst), "l"(src) : "memory");
}
#define CP_COMMIT() asm volatile("cp.async.commit_group;" ::: "memory")
#define CP_WAIT1()  asm volatile("cp.async.wait_group 1;" ::: "memory")

__device__ __forceinline__ void mulf2(float2& d, float a) {
    float2 s = make_float2(a, a);
    asm("mul.rn.f32x2 %0, %0, %1;"
        : "+l"(*reinterpret_cast<unsigned long long*>(&d))
        : "l"(*reinterpret_cast<const unsigned long long*>(&s)));
}

// ===========================================================================
// Prologue: rna-round H and W into scratch (plain layout — round 5 version).
// ===========================================================================
#define HN4 (B_ * S_ * HID_ / 4)
#define WN4 (HID_ * HID_ / 4)
#define RND_BLOCKS ((HN4 + 3 * WN4) / 256)

__global__ __launch_bounds__(256) void round_inputs(
    const float* __restrict__ H, const float* __restrict__ Wq,
    const float* __restrict__ Wk, const float* __restrict__ Wv)
{
    const int i = blockIdx.x * 256 + threadIdx.x;
    const float* src;
    float* dst;
    int j = i;
    if (j < HN4) { src = H; dst = g_h; }
    else if ((j -= HN4) < WN4) { src = Wq; dst = g_w[0]; }
    else if ((j -= WN4) < WN4) { src = Wk; dst = g_w[1]; }
    else { j -= WN4; src = Wv; dst = g_w[2]; }
    float4 v = ((const float4*)src)[j];
    uint4 o;
    o.x = f2tf32(v.x); o.y = f2tf32(v.y);
    o.z = f2tf32(v.z); o.w = f2tf32(v.w);
    ((uint4*)dst)[j] = o;
}

// ===========================================================================
// QKV projection via mma.sync tf32 + cp.async 3-stage pipeline (round 5).
// Only change: K-projection output written d-permuted for attn's LDS.64.
// ===========================================================================
#define QLDA 36
#define QSTG_W (128 * QLDA)
#define QB_OFF (3 * QSTG_W)
#define QKV_SMEM (6 * QSTG_W * 4)

extern __shared__ uint32_t qkv_sm[];

__global__ __launch_bounds__(256) void qkv_mma(
    const float* __restrict__ bq, const float* __restrict__ bk,
    const float* __restrict__ bv)
{
    const int proj = blockIdx.z;
    const float* Wsel = g_w[proj];
    const float* bias = (proj == 0) ? bq : (proj == 1) ? bk : bv;
    float* out        = (proj == 0) ? g_q : (proj == 1) ? g_k : g_v;

    const int m0 = blockIdx.y * 128;
    const int n0 = blockIdx.x * 128;

    const int t    = threadIdx.x;
    const int lane = t & 31;
    const int wid  = t >> 5;
    const int wm   = wid & 3;
    const int wn   = wid >> 2;
    const int g    = lane >> 2;
    const int tig  = lane & 3;

    const uint32_t sbase = smem_u32(qkv_sm);

    float acc[2][8][4];
    #pragma unroll
    for (int i = 0; i < 2; i++)
        #pragma unroll
        for (int j = 0; j < 8; j++)
            #pragma unroll
            for (int c = 0; c < 4; c++) acc[i][j][c] = 0.0f;

    auto cp_stage = [&](int st, int slot) {
        const int k0 = st * 32;
        const float* hA = g_h + (size_t)m0 * HID_ + k0;
        const float* wB = Wsel + (size_t)n0 * HID_ + k0;
        #pragma unroll
        for (int j = 0; j < 4; j++) {
            const int c = t + j * 256;
            const int r = c >> 3, cc = (c & 7) * 4;
            cp16(sbase + (uint32_t)(slot * QSTG_W + r * QLDA + cc) * 4,
                 hA + (size_t)r * HID_ + cc);
            cp16(sbase + (uint32_t)(QB_OFF + slot * QSTG_W + r * QLDA + cc) * 4,
                 wB + (size_t)r * HID_ + cc);
        }
    };

    cp_stage(0, 0); CP_COMMIT();
    cp_stage(1, 1); CP_COMMIT();

    for (int s = 0; s < 32; s++) {
        CP_WAIT1();
        __syncthreads();
        if (s + 2 < 32) cp_stage(s + 2, (s + 2) % 3);
        CP_COMMIT();

        const uint32_t* A  = qkv_sm + (s % 3) * QSTG_W;
        const uint32_t* Bs = qkv_sm + QB_OFF + (s % 3) * QSTG_W;

        #pragma unroll
        for (int kk = 0; kk < 4; kk++) {
            const int kb = kk * 8;
            uint32_t af[2][4], bf[8][2];
            #pragma unroll
            for (int tm = 0; tm < 2; tm++) {
                const int mr = wm * 32 + tm * 16;
                af[tm][0] = A[(mr + g) * QLDA + kb + tig];
                af[tm][1] = A[(mr + g + 8) * QLDA + kb + tig];
                af[tm][2] = A[(mr + g) * QLDA + kb + tig + 4];
                af[tm][3] = A[(mr + g + 8) * QLDA + kb + tig + 4];
            }
            #pragma unroll
            for (int tn = 0; tn < 8; tn++) {
                const int nr = wn * 64 + tn * 8;
                bf[tn][0] = Bs[(nr + g) * QLDA + kb + tig];
                bf[tn][1] = Bs[(nr + g) * QLDA + kb + tig + 4];
            }
            #pragma unroll
            for (int tm = 0; tm < 2; tm++)
                #pragma unroll
                for (int tn = 0; tn < 8; tn++)
                    mma_tf32(acc[tm][tn], af[tm], bf[tn]);
        }
    }

    // Epilogue (rna-rounded). K written d-permuted; Q/V plain float2.
    #pragma unroll
    for (int tm = 0; tm < 2; tm++) {
        const int m = m0 + wm * 32 + tm * 16 + g;
        const int bb = m >> 11;
        const int ss = m & 2047;
        #pragma unroll
        for (int tn = 0; tn < 8; tn++) {
            const int n = n0 + wn * 64 + tn * 8 + tig * 2;
            const int h = n >> 6;
            const int d = n & 63;
            const float2 bv2 = *(const float2*)(bias + n);
            float* base = out + ((size_t)(bb * NH_ + h) * S_) * HD_;
            const float v00 = __uint_as_float(f2tf32(acc[tm][tn][0] + bv2.x));
            const float v01 = __uint_as_float(f2tf32(acc[tm][tn][1] + bv2.y));
            const float v10 = __uint_as_float(f2tf32(acc[tm][tn][2] + bv2.x));
            const float v11 = __uint_as_float(f2tf32(acc[tm][tn][3] + bv2.y));
            if (proj != 1) {
                *(float2*)(base + (size_t)ss * HD_ + d) = make_float2(v00, v01);
                *(float2*)(base + (size_t)(ss + 8) * HD_ + d) = make_float2(v10, v11);
            } else {
                // d&7 == 2*tig. pos(2tig) = ((tig&1)<<2)|(tig>>1); pos(2tig+1)=pos+2
                const int dbase = d - 2 * tig;
                const int pos0 = ((tig & 1) << 2) | (tig >> 1);
                float* r0 = base + (size_t)ss * HD_ + dbase;
                float* r1 = base + (size_t)(ss + 8) * HD_ + dbase;
                r0[pos0] = v00; r0[pos0 + 2] = v01;
                r1[pos0] = v10; r1[pos0 + 2] = v11;
            }
        }
    }
}

// ===========================================================================
// Flash attention (round 5 structure). Change: K smem LDK=72 (≡8 mod 32) so
// the d-permuted K fragments load as conflict-free LDS.64.
// Smem words: KS[2]@0/4608, VS[2]@9216/13568, PS@17920, MSK@26624.
// ===========================================================================
#define LDK 72
#define LDV 68
#define LDP 68
#define KBUF_W (64 * LDK)              // 4608
#define VBUF_W (64 * LDV)              // 4352
#define VS_OFF (2 * KBUF_W)            // 9216
#define PS_OFF (VS_OFF + 2 * VBUF_W)   // 17920
#define MSK_OFF (PS_OFF + 8 * 16 * LDP) // 26624
#define AT_SMEM ((MSK_OFF + 2048) * 4)  // 114688 B

extern __shared__ uint32_t at_sm[];

__global__ void __launch_bounds__(256, 2) attn_mma(
    const float* __restrict__ mask, float* __restrict__ out)
{
    const int bh = blockIdx.y;
    const int bb = bh >> 4;
    const int h  = bh & 15;
    const int q0 = blockIdx.x * 128;

    const float* Q = g_q + (size_t)bh * S_ * HD_;
    const float* K = g_k + (size_t)bh * S_ * HD_;
    const float* V = g_v + (size_t)bh * S_ * HD_;
    const float* mrow = mask + (size_t)bb * S_;

    const int t    = threadIdx.x;
    const int lane = t & 31;
    const int w    = t >> 5;
    const int g    = lane >> 2;
    const int tig  = lane & 3;

    const uint32_t sbase = smem_u32(at_sm);
    float* msk = (float*)(at_sm + MSK_OFF);

    #pragma unroll
    for (int i = t; i < 512; i += 256) {
        float4 m4 = ((const float4*)mrow)[i];
        m4.x *= LOG2E; m4.y *= LOG2E; m4.z *= LOG2E; m4.w *= LOG2E;
        ((float4*)msk)[i] = m4;
    }

    const float SC = 0.125f * LOG2E;
    uint32_t qf[8][4];
    {
        const float* q0p = Q + (size_t)(q0 + w * 16 + g) * HD_;
        const float* q1p = q0p + 8 * HD_;
        #pragma unroll
        for (int kb = 0; kb < 8; kb++) {
            qf[kb][0] = f2tf32(SC * q0p[kb * 8 + tig]);
            qf[kb][1] = f2tf32(SC * q1p[kb * 8 + tig]);
            qf[kb][2] = f2tf32(SC * q0p[kb * 8 + tig + 4]);
            qf[kb][3] = f2tf32(SC * q1p[kb * 8 + tig + 4]);
        }
    }

    auto cp_tile = [&](int tile, int buf) {
        const int kv0 = tile * 64;
        #pragma unroll
        for (int j = 0; j < 4; j++) {
            const int c = t + j * 256;
            const int r = c >> 4, cc = (c & 15) * 4;
            cp16(sbase + (uint32_t)(buf * KBUF_W + r * LDK + cc) * 4,
                 K + (size_t)(kv0 + r) * HD_ + cc);
            cp16(sbase + (uint32_t)(VS_OFF + buf * VBUF_W + r * LDV + cc) * 4,
                 V + (size_t)(kv0 + r) * HD_ + cc);
        }
    };

    cp_tile(0, 0); CP_COMMIT();

    float2 oa[8][2];
    #pragma unroll
    for (int nt = 0; nt < 8; nt++) {
        oa[nt][0] = make_float2(0.f, 0.f);
        oa[nt][1] = make_float2(0.f, 0.f);
    }
    float m0 = -INFINITY, m1 = -INFINITY, l0 = 0.0f, l1 = 0.0f;

    for (int it = 0; it < 32; it++) {
        const int buf = it & 1;
        if (it + 1 < 32) cp_tile(it + 1, buf ^ 1);
        CP_COMMIT();
        CP_WAIT1();
        __syncthreads();

        const uint32_t* Ks = at_sm + buf * KBUF_W;
        const uint32_t* Vs = at_sm + VS_OFF + buf * VBUF_W;
        uint32_t* Ps = at_sm + PS_OFF + w * (16 * LDP);
        const float* mk_s = msk + it * 64;

        // S = Q K^T: K fragments conflict-free LDS.64 (d-permuted, LDK≡8 mod 32)
        float sacc[8][4];
        #pragma unroll
        for (int nt = 0; nt < 8; nt++)
            #pragma unroll
            for (int c = 0; c < 4; c++) sacc[nt][c] = 0.0f;

        #pragma unroll
        for (int kb = 0; kb < 8; kb++) {
            const uint32_t* kp = Ks + g * LDK + kb * 8 + 2 * tig;
            #pragma unroll
            for (int nt = 0; nt < 8; nt++) {
                uint2 b = *(const uint2*)&kp[nt * 8 * LDK];
                mma_tf32b(sacc[nt], qf[kb], b.x, b.y);
            }
        }

        float mx0 = m0, mx1 = m1;
        #pragma unroll
        for (int nt = 0; nt < 8; nt++) {
            const float2 mk = *(const float2*)&mk_s[nt * 8 + 2 * tig];
            sacc[nt][0] += mk.x; sacc[nt][1] += mk.y;
            sacc[nt][2] += mk.x; sacc[nt][3] += mk.y;
            mx0 = fmaxf(mx0, fmaxf(sacc[nt][0], sacc[nt][1]));
            mx1 = fmaxf(mx1, fmaxf(sacc[nt][2], sacc[nt][3]));
        }
        mx0 = fmaxf(mx0, __shfl_xor_sync(0xffffffffu, mx0, 1));
        mx0 = fmaxf(mx0, __shfl_xor_sync(0xffffffffu, mx0, 2));
        mx1 = fmaxf(mx1, __shfl_xor_sync(0xffffffffu, mx1, 1));
        mx1 = fmaxf(mx1, __shfl_xor_sync(0xffffffffu, mx1, 2));

        const float alpha0 = ex2(m0 - mx0);
        const float alpha1 = ex2(m1 - mx1);
        m0 = mx0; m1 = mx1;

        float s0 = 0.0f, s1 = 0.0f;
        #pragma unroll
        for (int nt = 0; nt < 8; nt++) {
            const uint32_t u0 = f2tf32(ex2(sacc[nt][0] - mx0));
            const uint32_t u1 = f2tf32(ex2(sacc[nt][1] - mx0));
            const uint32_t u2 = f2tf32(ex2(sacc[nt][2] - mx1));
            const uint32_t u3 = f2tf32(ex2(sacc[nt][3] - mx1));
            s0 += __uint_as_float(u0) + __uint_as_float(u1);
            s1 += __uint_as_float(u2) + __uint_as_float(u3);
            *(uint2*)&Ps[g * LDP + nt * 8 + 2 * tig] = make_uint2(u0, u1);
            *(uint2*)&Ps[(g + 8) * LDP + nt * 8 + 2 * tig] = make_uint2(u2, u3);
        }
        s0 += __shfl_xor_sync(0xffffffffu, s0, 1);
        s0 += __shfl_xor_sync(0xffffffffu, s0, 2);
        s1 += __shfl_xor_sync(0xffffffffu, s1, 1);
        s1 += __shfl_xor_sync(0xffffffffu, s1, 2);
        l0 = l0 * alpha0 + s0;
        l1 = l1 * alpha1 + s1;

        #pragma unroll
        for (int nt = 0; nt < 8; nt++) {
            mulf2(oa[nt][0], alpha0);
            mulf2(oa[nt][1], alpha1);
        }
        __syncwarp();

        // O += P V
        #pragma unroll
        for (int kb = 0; kb < 8; kb++) {
            uint32_t a[4];
            a[0] = Ps[g * LDP + kb * 8 + tig];
            a[1] = Ps[(g + 8) * LDP + kb * 8 + tig];
            a[2] = Ps[g * LDP + kb * 8 + tig + 4];
            a[3] = Ps[(g + 8) * LDP + kb * 8 + tig + 4];
            const uint32_t* vp = Vs + (kb * 8 + tig) * LDV + g;
            #pragma unroll
            for (int nt = 0; nt < 8; nt++)
                mma_tf32b((float*)&oa[nt][0], a,
                          vp[nt * 8], vp[4 * LDV + nt * 8]);
        }
        __syncthreads();
    }

    const float inv0 = 1.0f / l0;
    const float inv1 = 1.0f / l1;
    const int r0 = q0 + w * 16 + g;
    float* o0 = out + ((size_t)(bb * S_ + r0)) * HID_ + h * 64;
    float* o1 = out + ((size_t)(bb * S_ + r0 + 8)) * HID_ + h * 64;
    #pragma unroll
    for (int nt = 0; nt < 8; nt++) {
        const int c = nt * 8 + 2 * tig;
        float2 v0, v1;
        v0.x = oa[nt][0].x * inv0; v0.y = oa[nt][0].y * inv0;
        v1.x = oa[nt][1].x * inv1; v1.y = oa[nt][1].y * inv1;
        *(float2*)(o0 + c) = v0;
        *(float2*)(o1 + c) = v1;
    }
}

// ===========================================================================
extern "C" void kernel_launch(void* const* d_in, const int* in_sizes, int n_in,
                              void* d_out, int out_size)
{
    const float* H    = (const float*)d_in[0];
    const float* mask = (const float*)d_in[1];
    const float* Wq   = (const float*)d_in[2];
    const float* bq   = (const float*)d_in[3];
    const float* Wk   = (const float*)d_in[4];
    const float* bk   = (const float*)d_in[5];
    const float* Wv   = (const float*)d_in[6];
    const float* bv   = (const float*)d_in[7];
    float* out = (float*)d_out;

    cudaFuncSetAttribute(qkv_mma,
                         cudaFuncAttributeMaxDynamicSharedMemorySize, QKV_SMEM);
    cudaFuncSetAttribute(attn_mma,
                         cudaFuncAttributeMaxDynamicSharedMemorySize, AT_SMEM);

    round_inputs<<<RND_BLOCKS, 256>>>(H, Wq, Wk, Wv);

    dim3 gq(HID_ / 128, (B_ * S_) / 128, 3);
    qkv_mma<<<gq, 256, QKV_SMEM>>>(bq, bk, bv);

    dim3 ga(S_ / 128, B_ * NH_);
    attn_mma<<<ga, 256, AT_SMEM>>>(mask, out);
}